// round 7
// baseline (speedup 1.0000x reference)
#include <cuda_runtime.h>
#include <cstdint>

// ---- problem constants ----
#define N_OBJ     16
#define DIM_IN    256
#define NCOLS     64
#define BM        256               // rows per block
#define ROWSTRIDE 4096              // floats between batch rows of x
#define OUTSTRIDE 1024              // floats between batch rows of out
#define KC        16                // k per pipeline chunk
#define NCHUNK    (DIM_IN / KC)     // 16

#define ASTR         20                      // A smem words per row (bank-CF)
#define ASTAGE_WORDS (BM * ASTR)             // 5120 words = 20 KB
#define SM_A         0
#define SM_W         (2 * ASTAGE_WORDS * 4)  // 40960
#define SM_BIAS      (SM_W + 65536)          // 106496
#define SMEM_BYTES   (SM_BIAS + 256 + 256)   // ~107 KB -> 2 blocks/SM

__device__ __forceinline__ uint32_t f2tf32(float f) {
    uint32_t r; asm("cvt.rna.tf32.f32 %0, %1;" : "=r"(r) : "f"(f)); return r;
}
__device__ __forceinline__ void cp16(uint32_t dst, const float* src) {
    asm volatile("cp.async.cg.shared.global [%0], [%1], 16;" :: "r"(dst), "l"(src));
}

__global__ void __launch_bounds__(256, 2)
objdec_kernel(const float* __restrict__ x,
              const float* __restrict__ W,
              const float* __restrict__ bias,
              float* __restrict__ out)
{
    extern __shared__ char smem[];
    float*    Asm = (float*)(smem + SM_A);      // 2 stages, raw fp32 x
    uint32_t* Wf  = (uint32_t*)(smem + SM_W);   // W tf32, fragment-major
    float*    bsm = (float*)(smem + SM_BIAS);

    const int tid   = threadIdx.x;
    const int warp  = tid >> 5;
    const int lane  = tid & 31;
    const int o     = blockIdx.y;
    const int rbase = blockIdx.x * BM;
    const float* xg = x + (size_t)rbase * ROWSTRIDE + o * DIM_IN;

    // ---- cp.async addressing: thread tid owns row tid; 4 x 16B per chunk ----
    const uint32_t abase = (uint32_t)__cvta_generic_to_shared(Asm);
    const uint32_t adst  = abase + tid * (ASTR * 4);      // row base, stage 0
    const float*   asrc  = xg + (size_t)tid * ROWSTRIDE;  // row base in gmem

    // ---- prefetch chunks 0 and 1 ----
    #pragma unroll
    for (int q = 0; q < 4; ++q) cp16(adst + q * 16, asrc + q * 4);
    asm volatile("cp.async.commit_group;\n");
    #pragma unroll
    for (int q = 0; q < 4; ++q)
        cp16(adst + ASTAGE_WORDS * 4 + q * 16, asrc + KC + q * 4);
    asm volatile("cp.async.commit_group;\n");

    // ---- stage W[o] -> fragment-major smem, RNA tf32 (one time) ----
    // word addr = ((s*8 + j)*32 + (g*4 + (c&3)))*2 + (c>>2)
    //   where n = j*8+g (output col), d = s*8+c (k index)
    {
        const float4* Wg4 = (const float4*)(W + (size_t)o * (NCOLS * DIM_IN));
        #pragma unroll
        for (int i = 0; i < 16; ++i) {
            int idx4 = tid + i * 256;
            int m = idx4 * 4;                 // linear float index
            float4 v = Wg4[idx4];
            int k  = m & 7;                   // 0 or 4
            int d  = (m >> 3) & 255;
            int n0 = (m >> 12) * 16 + ((m >> 11) & 1) * 8 + k;
            int j  = n0 >> 3;
            int s  = d >> 3;
            int c  = d & 7;
            int slot  = c >> 2;
            int cl    = c & 3;
            uint32_t base = ((s * 8 + j) * 32) * 2 + slot;
            float vv[4] = {v.x, v.y, v.z, v.w};
            #pragma unroll
            for (int t = 0; t < 4; ++t) {
                int g = (n0 & 7) + t;         // k=0 -> g 0..3, k=4 -> g 4..7
                Wf[base + (g * 4 + cl) * 2] = f2tf32(vv[t]);
            }
        }
        if (tid < NCOLS) bsm[tid] = bias[o * NCOLS + tid];
    }

    // ---- warp tiling: 4 mwarps x 2 nwarps; warp = 64 rows x 32 cols ----
    const int mw = warp & 3;
    const int nw = warp >> 2;
    const int g  = lane >> 2;
    const int c  = lane & 3;

    float acc[4][4][4];
    #pragma unroll
    for (int mi = 0; mi < 4; ++mi)
        #pragma unroll
        for (int j = 0; j < 4; ++j)
            #pragma unroll
            for (int q = 0; q < 4; ++q) acc[mi][j][q] = 0.0f;

    const int aoff = (mw * 64 + g) * ASTR + c;    // word offset, mi=0, ks=0

    for (int ck = 0; ck < NCHUNK; ++ck) {
        if (ck < NCHUNK - 1) {
            asm volatile("cp.async.wait_group 1;\n" ::: "memory");
        } else {
            asm volatile("cp.async.wait_group 0;\n" ::: "memory");
        }
        __syncthreads();

        const float* Ab = Asm + (ck & 1) * ASTAGE_WORDS + aoff;
        #pragma unroll
        for (int ks = 0; ks < 2; ++ks) {
            // A fragments: 16 x LDS.32 (conflict-free, raw fp32 bits as tf32)
            uint32_t a[4][4];
            #pragma unroll
            for (int mi = 0; mi < 4; ++mi) {
                const float* Ar = Ab + mi * 16 * ASTR + ks * 8;
                a[mi][0] = __float_as_uint(Ar[0]);
                a[mi][1] = __float_as_uint(Ar[8 * ASTR]);
                a[mi][2] = __float_as_uint(Ar[4]);
                a[mi][3] = __float_as_uint(Ar[8 * ASTR + 4]);
            }
            // B fragments: 4 x LDS.64
            const int s = ck * 2 + ks;
            uint2 b[4];
            #pragma unroll
            for (int j = 0; j < 4; ++j) {
                b[j] = *(const uint2*)(Wf + ((s * 8 + nw * 4 + j) * 32 + lane) * 2);
            }
            // 16 MMAs
            #pragma unroll
            for (int mi = 0; mi < 4; ++mi) {
                #pragma unroll
                for (int j = 0; j < 4; ++j) {
                    asm volatile(
                        "mma.sync.aligned.m16n8k8.row.col.f32.tf32.tf32.f32 "
                        "{%0,%1,%2,%3}, {%4,%5,%6,%7}, {%8,%9}, {%0,%1,%2,%3};\n"
                        : "+f"(acc[mi][j][0]), "+f"(acc[mi][j][1]),
                          "+f"(acc[mi][j][2]), "+f"(acc[mi][j][3])
                        : "r"(a[mi][0]), "r"(a[mi][1]), "r"(a[mi][2]), "r"(a[mi][3]),
                          "r"(b[j].x), "r"(b[j].y));
                }
            }
        }

        __syncthreads();   // all warps done reading this stage
        if (ck + 2 < NCHUNK) {
            const uint32_t dstb = adst + (ck & 1) * (ASTAGE_WORDS * 4);
            const float*   srcb = asrc + (ck + 2) * KC;
            #pragma unroll
            for (int q = 0; q < 4; ++q) cp16(dstb + q * 16, srcb + q * 4);
            asm volatile("cp.async.commit_group;\n");
        }
    }

    // ---- epilogue: bias + float2 stores ----
    #pragma unroll
    for (int mi = 0; mi < 4; ++mi) {
        const int row0 = rbase + mw * 64 + mi * 16 + g;
        const int row1 = row0 + 8;
        #pragma unroll
        for (int j = 0; j < 4; ++j) {
            const int col = nw * 32 + j * 8 + 2 * c;
            float bv0 = bsm[col];
            float bv1 = bsm[col + 1];
            float2 v0 = make_float2(acc[mi][j][0] + bv0, acc[mi][j][1] + bv1);
            float2 v1 = make_float2(acc[mi][j][2] + bv0, acc[mi][j][3] + bv1);
            float* p0 = out + (size_t)row0 * OUTSTRIDE + o * NCOLS + col;
            float* p1 = out + (size_t)row1 * OUTSTRIDE + o * NCOLS + col;
            *reinterpret_cast<float2*>(p0) = v0;
            *reinterpret_cast<float2*>(p1) = v1;
        }
    }
}

extern "C" void kernel_launch(void* const* d_in, const int* in_sizes, int n_in,
                              void* d_out, int out_size)
{
    (void)in_sizes; (void)n_in; (void)out_size;
    const float* x = (const float*)d_in[0];
    const float* W = (const float*)d_in[1];
    const float* b = (const float*)d_in[2];
    float* out = (float*)d_out;

    cudaFuncSetAttribute(objdec_kernel,
                         cudaFuncAttributeMaxDynamicSharedMemorySize, SMEM_BYTES);

    dim3 grid(16384 / BM, N_OBJ);
    objdec_kernel<<<grid, 256, SMEM_BYTES>>>(x, W, b, out);
}

// round 8
// speedup vs baseline: 1.2003x; 1.2003x over previous
#include <cuda_runtime.h>
#include <cstdint>

// ---- problem constants ----
#define N_OBJ     16
#define DIM_IN    256
#define NCOLS     64
#define BM        128
#define ROWSTRIDE 4096              // floats between batch rows of x
#define OUTSTRIDE 1024              // floats between batch rows of out
#define KC        32                // k per pipeline chunk
#define NCHUNK    (DIM_IN / KC)     // 8

#define ASTR         36                      // A smem words per row (bank-CF)
#define ASTAGE_WORDS (BM * ASTR)             // 4608 words = 18 KB
#define SM_A         0
#define SM_W         (2 * ASTAGE_WORDS * 4)  // 36864
#define SM_BIAS      (SM_W + 65536)          // 102400
#define SMEM_BYTES   (SM_BIAS + 512)         // 102912 -> 2 blocks/SM

__device__ __forceinline__ uint32_t f2tf32(float f) {
    uint32_t r; asm("cvt.rna.tf32.f32 %0, %1;" : "=r"(r) : "f"(f)); return r;
}
__device__ __forceinline__ void cp16(uint32_t dst, const float* src) {
    asm volatile("cp.async.cg.shared.global [%0], [%1], 16;" :: "r"(dst), "l"(src));
}

__global__ void __launch_bounds__(256, 2)
objdec_kernel(const float* __restrict__ x,
              const float* __restrict__ W,
              const float* __restrict__ bias,
              float* __restrict__ out)
{
    extern __shared__ char smem[];
    float*    Asm = (float*)(smem + SM_A);      // 2 stages, raw fp32 x
    uint32_t* Wf  = (uint32_t*)(smem + SM_W);   // W tf32, fragment-major
    float*    bsm = (float*)(smem + SM_BIAS);

    const int tid   = threadIdx.x;
    const int warp  = tid >> 5;
    const int lane  = tid & 31;
    const int o     = blockIdx.y;
    const int rbase = blockIdx.x * BM;
    const float* xg = x + (size_t)rbase * ROWSTRIDE + o * DIM_IN;

    // ---- cp.async addressing: 8 threads per row, 128B contiguous/4-row group ----
    // lin = tid + q*256 ; row = lin>>3, quad = lin&7  (4 x 16B per thread/chunk)
    const float* asrc[4];
    uint32_t adst[4];
    {
        uint32_t abase = (uint32_t)__cvta_generic_to_shared(Asm);
        #pragma unroll
        for (int q = 0; q < 4; ++q) {
            int lin  = tid + q * 256;
            int row  = lin >> 3;
            int quad = lin & 7;
            asrc[q] = xg + (size_t)row * ROWSTRIDE + quad * 4;
            adst[q] = abase + (row * ASTR + quad * 4) * 4;
        }
    }

    // ---- prefetch chunks 0 and 1 ----
    #pragma unroll
    for (int q = 0; q < 4; ++q) cp16(adst[q], asrc[q]);
    asm volatile("cp.async.commit_group;\n");
    #pragma unroll
    for (int q = 0; q < 4; ++q)
        cp16(adst[q] + ASTAGE_WORDS * 4, asrc[q] + KC);
    asm volatile("cp.async.commit_group;\n");

    // ---- stage W[o] -> fragment-major smem, RNA tf32 (one time) ----
    // store W[n][d] at ((s*8 + j)*32 + g*4 + cl)*2 + slot
    //   n = j*8 + g, d = s*8 + cl + 4*slot
    {
        const float4* Wg4 = (const float4*)(W + (size_t)o * (NCOLS * DIM_IN));
        #pragma unroll
        for (int i = 0; i < 16; ++i) {
            int idx4 = tid + i * 256;
            int m = idx4 * 4;                 // linear float index
            float4 v = Wg4[idx4];
            int k  = m & 7;                   // 0 or 4
            int d  = (m >> 3) & 255;
            int n0 = (m >> 12) * 16 + ((m >> 11) & 1) * 8 + k;
            int j  = n0 >> 3;
            int s  = d >> 3;
            int c  = d & 7;
            int slot = c >> 2;
            int cl   = c & 3;
            uint32_t base = ((s * 8 + j) * 32) * 2 + slot;
            float vv[4] = {v.x, v.y, v.z, v.w};
            #pragma unroll
            for (int t = 0; t < 4; ++t) {
                int g = (n0 & 7) + t;         // k=0 -> g 0..3, k=4 -> g 4..7
                Wf[base + (g * 4 + cl) * 2] = f2tf32(vv[t]);
            }
        }
        if (tid < NCOLS) bsm[tid] = bias[o * NCOLS + tid];
    }

    // ---- warp tiling: 4 mwarps x 2 nwarps; warp = 32 rows x 32 cols ----
    const int mw = warp & 3;
    const int nw = warp >> 2;
    const int g  = lane >> 2;
    const int c  = lane & 3;

    float acc[2][4][4];
    #pragma unroll
    for (int mi = 0; mi < 2; ++mi)
        #pragma unroll
        for (int j = 0; j < 4; ++j)
            #pragma unroll
            for (int q = 0; q < 4; ++q) acc[mi][j][q] = 0.0f;

    const int aoff = (mw * 32 + g) * ASTR + c;      // word offset, mi=0

    for (int ck = 0; ck < NCHUNK; ++ck) {
        if (ck < NCHUNK - 1) {
            asm volatile("cp.async.wait_group 1;\n" ::: "memory");
        } else {
            asm volatile("cp.async.wait_group 0;\n" ::: "memory");
        }
        __syncthreads();

        const float* Ab = Asm + (ck & 1) * ASTAGE_WORDS + aoff;
        #pragma unroll
        for (int kb = 0; kb < KC; kb += 8) {
            // A fragments: 8 x LDS.32, raw fp32 bits as tf32 (truncated by HW)
            uint32_t a0[4], a1[4];
            a0[0] = __float_as_uint(Ab[kb]);
            a0[1] = __float_as_uint(Ab[8 * ASTR + kb]);
            a0[2] = __float_as_uint(Ab[kb + 4]);
            a0[3] = __float_as_uint(Ab[8 * ASTR + kb + 4]);
            a1[0] = __float_as_uint(Ab[16 * ASTR + kb]);
            a1[1] = __float_as_uint(Ab[24 * ASTR + kb]);
            a1[2] = __float_as_uint(Ab[16 * ASTR + kb + 4]);
            a1[3] = __float_as_uint(Ab[24 * ASTR + kb + 4]);

            // B fragments: 4 x LDS.64 (fragment-major W)
            const int s = ck * 4 + (kb >> 3);       // global k-step
            uint2 b[4];
            #pragma unroll
            for (int j = 0; j < 4; ++j) {
                b[j] = *(const uint2*)(Wf + ((s * 8 + nw * 4 + j) * 32 + lane) * 2);
            }

            // 8 MMAs
            #pragma unroll
            for (int j = 0; j < 4; ++j) {
                asm volatile(
                    "mma.sync.aligned.m16n8k8.row.col.f32.tf32.tf32.f32 "
                    "{%0,%1,%2,%3}, {%4,%5,%6,%7}, {%8,%9}, {%0,%1,%2,%3};\n"
                    : "+f"(acc[0][j][0]), "+f"(acc[0][j][1]),
                      "+f"(acc[0][j][2]), "+f"(acc[0][j][3])
                    : "r"(a0[0]), "r"(a0[1]), "r"(a0[2]), "r"(a0[3]),
                      "r"(b[j].x), "r"(b[j].y));
                asm volatile(
                    "mma.sync.aligned.m16n8k8.row.col.f32.tf32.tf32.f32 "
                    "{%0,%1,%2,%3}, {%4,%5,%6,%7}, {%8,%9}, {%0,%1,%2,%3};\n"
                    : "+f"(acc[1][j][0]), "+f"(acc[1][j][1]),
                      "+f"(acc[1][j][2]), "+f"(acc[1][j][3])
                    : "r"(a1[0]), "r"(a1[1]), "r"(a1[2]), "r"(a1[3]),
                      "r"(b[j].x), "r"(b[j].y));
            }
        }

        __syncthreads();   // all warps done reading this stage
        if (ck + 2 < NCHUNK) {
            const int koff = (ck + 2) * KC;
            const uint32_t soff = (ck & 1) * (ASTAGE_WORDS * 4);
            #pragma unroll
            for (int q = 0; q < 4; ++q) cp16(adst[q] + soff, asrc[q] + koff);
            asm volatile("cp.async.commit_group;\n");
        }
    }

    // ---- epilogue: bias + float2 stores ----
    #pragma unroll
    for (int mi = 0; mi < 2; ++mi) {
        const int row0 = rbase + mw * 32 + mi * 16 + g;
        const int row1 = row0 + 8;
        #pragma unroll
        for (int j = 0; j < 4; ++j) {
            const int col = nw * 32 + j * 8 + 2 * c;
            float bv0 = bsm[col];
            float bv1 = bsm[col + 1];
            float2 v0 = make_float2(acc[mi][j][0] + bv0, acc[mi][j][1] + bv1);
            float2 v1 = make_float2(acc[mi][j][2] + bv0, acc[mi][j][3] + bv1);
            float* p0 = out + (size_t)row0 * OUTSTRIDE + o * NCOLS + col;
            float* p1 = out + (size_t)row1 * OUTSTRIDE + o * NCOLS + col;
            *reinterpret_cast<float2*>(p0) = v0;
            *reinterpret_cast<float2*>(p1) = v1;
        }
    }
}

extern "C" void kernel_launch(void* const* d_in, const int* in_sizes, int n_in,
                              void* d_out, int out_size)
{
    (void)in_sizes; (void)n_in; (void)out_size;
    const float* x = (const float*)d_in[0];
    const float* W = (const float*)d_in[1];
    const float* b = (const float*)d_in[2];
    float* out = (float*)d_out;

    cudaFuncSetAttribute(objdec_kernel,
                         cudaFuncAttributeMaxDynamicSharedMemorySize, SMEM_BYTES);

    dim3 grid(16384 / BM, N_OBJ);
    objdec_kernel<<<grid, 256, SMEM_BYTES>>>(x, W, b, out);
}

// round 11
// speedup vs baseline: 1.3073x; 1.0891x over previous
#include <cuda_runtime.h>
#include <cstdint>

// ---- problem constants ----
#define N_OBJ     16
#define DIM_IN    256
#define NCOLS     64
#define BM        128
#define ROWSTRIDE 4096              // floats between batch rows of x
#define OUTSTRIDE 1024              // floats between batch rows of out
#define KC        32                // k per pipeline chunk
#define NCHUNK    (DIM_IN / KC)     // 8
#define NSTAGE    3

#define ASTR         36                      // A smem words per row (bank-CF)
#define ASTAGE_WORDS (BM * ASTR)             // 4608 words = 18 KB
#define SM_BIAS      (NSTAGE * ASTAGE_WORDS * 4)   // 55296
#define SMEM_BYTES   (SM_BIAS + 256)               // 55552 -> 3 blocks/SM (smem)

// Fragment-major tf32 W: [obj][s(32)][j(8)][lane(32)][2 words] = 1 MB
__device__ uint32_t Wfrag_g[N_OBJ * 32 * 8 * 32 * 2];

__device__ __forceinline__ uint32_t f2tf32(float f) {
    uint32_t r; asm("cvt.rna.tf32.f32 %0, %1;" : "=r"(r) : "f"(f)); return r;
}
__device__ __forceinline__ void cp16(uint32_t dst, const float* src) {
    asm volatile("cp.async.cg.shared.global [%0], [%1], 16;" :: "r"(dst), "l"(src));
}

// ---- pre-kernel: build fragment-major tf32 W in global (runs once/graph) ----
__global__ void __launch_bounds__(256)
prep_kernel(const float* __restrict__ W)
{
    const int o   = blockIdx.x;
    const int tid = threadIdx.x;
    uint32_t* Wf = Wfrag_g + o * 16384;
    const float4* Wg4 = (const float4*)(W + (size_t)o * (NCOLS * DIM_IN));
    #pragma unroll
    for (int i = 0; i < 16; ++i) {
        int idx4 = tid + i * 256;
        int m = idx4 * 4;                 // linear float index within object
        float4 v = Wg4[idx4];
        int k  = m & 7;                   // 0 or 4
        int d  = (m >> 3) & 255;
        int n0 = (m >> 12) * 16 + ((m >> 11) & 1) * 8 + k;
        int j  = n0 >> 3;
        int s  = d >> 3;
        int c  = d & 7;
        int slot = c >> 2;
        int cl   = c & 3;
        uint32_t base = ((s * 8 + j) * 32) * 2 + slot;
        float vv[4] = {v.x, v.y, v.z, v.w};
        #pragma unroll
        for (int t = 0; t < 4; ++t) {
            int g = (n0 & 7) + t;         // k=0 -> g 0..3, k=4 -> g 4..7
            Wf[base + (g * 4 + cl) * 2] = f2tf32(vv[t]);
        }
    }
}

__global__ void __launch_bounds__(256, 3)
objdec_kernel(const float* __restrict__ x,
              const float* __restrict__ bias,
              float* __restrict__ out)
{
    extern __shared__ char smem[];
    float* Asm = (float*)smem;                  // 3 stages, raw fp32 x
    float* bsm = (float*)(smem + SM_BIAS);

    const int tid   = threadIdx.x;
    const int warp  = tid >> 5;
    const int lane  = tid & 31;
    const int o     = blockIdx.y;
    const int rbase = blockIdx.x * BM;
    const float* xg = x + (size_t)rbase * ROWSTRIDE + o * DIM_IN;

    // ---- cp.async addressing: 8 threads/row, 128B contiguous per 4-row group ----
    const float* asrc[4];
    uint32_t adst[4];
    {
        uint32_t abase = (uint32_t)__cvta_generic_to_shared(Asm);
        #pragma unroll
        for (int q = 0; q < 4; ++q) {
            int lin  = tid + q * 256;
            int row  = lin >> 3;
            int quad = lin & 7;
            asrc[q] = xg + (size_t)row * ROWSTRIDE + quad * 4;
            adst[q] = abase + (row * ASTR + quad * 4) * 4;
        }
    }

    // ---- prologue: chunk 0 -> stage 0, chunk 1 -> stage 1 ----
    #pragma unroll
    for (int q = 0; q < 4; ++q) cp16(adst[q], asrc[q]);
    asm volatile("cp.async.commit_group;\n");
    #pragma unroll
    for (int q = 0; q < 4; ++q)
        cp16(adst[q] + ASTAGE_WORDS * 4, asrc[q] + KC);
    asm volatile("cp.async.commit_group;\n");

    if (tid < NCOLS) bsm[tid] = bias[o * NCOLS + tid];

    // ---- warp tiling: 4 mwarps x 2 nwarps; warp = 32 rows x 32 cols ----
    const int mw = warp & 3;
    const int nw = warp >> 2;
    const int g  = lane >> 2;
    const int c  = lane & 3;

    float acc[2][4][4];
    #pragma unroll
    for (int mi = 0; mi < 2; ++mi)
        #pragma unroll
        for (int j = 0; j < 4; ++j)
            #pragma unroll
            for (int q = 0; q < 4; ++q) acc[mi][j][q] = 0.0f;

    const int aoff = (mw * 32 + g) * ASTR + c;
    const uint2* Wp = ((const uint2*)Wfrag_g) + (o * 8192) + (nw * 4) * 32 + lane;

    for (int ck = 0; ck < NCHUNK; ++ck) {
        if (ck < NCHUNK - 1) {
            asm volatile("cp.async.wait_group 1;\n" ::: "memory");
        } else {
            asm volatile("cp.async.wait_group 0;\n" ::: "memory");
        }
        __syncthreads();
        // stage (ck-1)%3 retired by the barrier above -> refill with chunk ck+2
        if (ck + 2 < NCHUNK) {
            const int koff = (ck + 2) * KC;
            const uint32_t soff = ((ck + 2) % NSTAGE) * (ASTAGE_WORDS * 4);
            #pragma unroll
            for (int q = 0; q < 4; ++q) cp16(adst[q] + soff, asrc[q] + koff);
            asm volatile("cp.async.commit_group;\n");
        }

        const float* Ab = Asm + (ck % NSTAGE) * ASTAGE_WORDS + aoff;
        #pragma unroll
        for (int kb = 0; kb < KC; kb += 8) {
            // A fragments: 8 x LDS.32 (raw fp32 bits, HW truncates to tf32)
            uint32_t a0[4], a1[4];
            a0[0] = __float_as_uint(Ab[kb]);
            a0[1] = __float_as_uint(Ab[8 * ASTR + kb]);
            a0[2] = __float_as_uint(Ab[kb + 4]);
            a0[3] = __float_as_uint(Ab[8 * ASTR + kb + 4]);
            a1[0] = __float_as_uint(Ab[16 * ASTR + kb]);
            a1[1] = __float_as_uint(Ab[24 * ASTR + kb]);
            a1[2] = __float_as_uint(Ab[16 * ASTR + kb + 4]);
            a1[3] = __float_as_uint(Ab[24 * ASTR + kb + 4]);

            // B fragments: 4 x LDG.64 from L2-resident fragment-major W
            const int s = ck * 4 + (kb >> 3);
            uint2 b[4];
            #pragma unroll
            for (int j = 0; j < 4; ++j) {
                b[j] = __ldg(Wp + (s * 8 + j) * 32);
            }

            // 8 MMAs
            #pragma unroll
            for (int j = 0; j < 4; ++j) {
                asm volatile(
                    "mma.sync.aligned.m16n8k8.row.col.f32.tf32.tf32.f32 "
                    "{%0,%1,%2,%3}, {%4,%5,%6,%7}, {%8,%9}, {%0,%1,%2,%3};\n"
                    : "+f"(acc[0][j][0]), "+f"(acc[0][j][1]),
                      "+f"(acc[0][j][2]), "+f"(acc[0][j][3])
                    : "r"(a0[0]), "r"(a0[1]), "r"(a0[2]), "r"(a0[3]),
                      "r"(b[j].x), "r"(b[j].y));
                asm volatile(
                    "mma.sync.aligned.m16n8k8.row.col.f32.tf32.tf32.f32 "
                    "{%0,%1,%2,%3}, {%4,%5,%6,%7}, {%8,%9}, {%0,%1,%2,%3};\n"
                    : "+f"(acc[1][j][0]), "+f"(acc[1][j][1]),
                      "+f"(acc[1][j][2]), "+f"(acc[1][j][3])
                    : "r"(a1[0]), "r"(a1[1]), "r"(a1[2]), "r"(a1[3]),
                      "r"(b[j].x), "r"(b[j].y));
            }
        }
    }

    // ---- epilogue: bias + float2 stores ----
    #pragma unroll
    for (int mi = 0; mi < 2; ++mi) {
        const int row0 = rbase + mw * 32 + mi * 16 + g;
        const int row1 = row0 + 8;
        #pragma unroll
        for (int j = 0; j < 4; ++j) {
            const int col = nw * 32 + j * 8 + 2 * c;
            float bv0 = bsm[col];
            float bv1 = bsm[col + 1];
            float2 v0 = make_float2(acc[mi][j][0] + bv0, acc[mi][j][1] + bv1);
            float2 v1 = make_float2(acc[mi][j][2] + bv0, acc[mi][j][3] + bv1);
            float* p0 = out + (size_t)row0 * OUTSTRIDE + o * NCOLS + col;
            float* p1 = out + (size_t)row1 * OUTSTRIDE + o * NCOLS + col;
            *reinterpret_cast<float2*>(p0) = v0;
            *reinterpret_cast<float2*>(p1) = v1;
        }
    }
}

extern "C" void kernel_launch(void* const* d_in, const int* in_sizes, int n_in,
                              void* d_out, int out_size)
{
    (void)in_sizes; (void)n_in; (void)out_size;
    const float* x = (const float*)d_in[0];
    const float* W = (const float*)d_in[1];
    const float* b = (const float*)d_in[2];
    float* out = (float*)d_out;

    cudaFuncSetAttribute(objdec_kernel,
                         cudaFuncAttributeMaxDynamicSharedMemorySize, SMEM_BYTES);

    prep_kernel<<<N_OBJ, 256>>>(W);
    dim3 grid(16384 / BM, N_OBJ);
    objdec_kernel<<<grid, 256, SMEM_BYTES>>>(x, b, out);
}